// round 10
// baseline (speedup 1.0000x reference)
#include <cuda_runtime.h>
#include <cstdint>

// Retrace_9844065042706 — affine-segment scan, cp.async staging, fused
// last-block compose (single kernel).
// Block = 4 b x 16 d over a 32-step segment (64 thr, 42.8KB smem -> 5
// resident blocks/SM). Per-segment record: loss quadratic in incoming carry
// (alpha, beta, delta) + carry map (A, M), stored dense seg-major.
// The 16th-arriving block of each b-group composes its 64 chains (L2-hot),
// the 512th-arriving b-group finalizer reduces partials and stores out[0].

#define RB 2048
#define RT 512
#define RD 16
#define SEG 16
#define SEGLEN 32
#define NJ (RT - 1)            // 511
#define BD (RB * RD)           // 32768 chains
#define NBL 4                  // b's per block
#define NTH 64                 // threads (4 b x 16 d)
#define NBG (RB / NBL)         // 512 b-groups

// smem (floats): 5 tensors [4][32][16] (+16 pad per b), then bp [4][33]
#define BSTR  528
#define TS    (NBL * BSTR)     // 2112
#define BPOFF (5 * TS)         // 10560
#define BPSTR 33
#define SMEM_FLOATS (BPOFF + NBL * BPSTR)   // 10692 -> 42768 B
#define SMEM_BYTES  (SMEM_FLOATS * 4)

static constexpr float GAMMA = 0.99f;

// Dense scratch, seg-major (chain-contiguous): 10 MB
__device__ float4 g4 [(size_t)SEG * BD];   // {A, M, beta, delta}
__device__ float  gal[(size_t)SEG * BD];   // alpha

__device__ unsigned int g_cnt_bg[NBG];     // zero-init, self-resetting
__device__ unsigned int g_cnt_all;         // zero-init, self-resetting
__device__ float        g_part[NBG];

__device__ __forceinline__ void cp16(uint32_t s, const void* g) {
    asm volatile("cp.async.cg.shared.global [%0], [%1], 16;" :: "r"(s), "l"(g));
}
__device__ __forceinline__ void cp4(uint32_t s, const void* g) {
    asm volatile("cp.async.ca.shared.global [%0], [%1], 4;" :: "r"(s), "l"(g));
}
__device__ __forceinline__ void cp_commit() { asm volatile("cp.async.commit_group;"); }
template <int N>
__device__ __forceinline__ void cp_wait() {
    asm volatile("cp.async.wait_group %0;" :: "n"(N));
}
__device__ __forceinline__ uint32_t smem_u32(const void* p) {
    return (uint32_t)__cvta_generic_to_shared(p);
}

// copy rows [k0, k0+16) of the tile (5 tensors + bp)
__device__ __forceinline__ void copy_half(
    float* sm, int tid, int bg, int lo, int k0,
    const float* __restrict__ E, const float* __restrict__ TQ,
    const float* __restrict__ TPP, const float* __restrict__ R,
    const float* __restrict__ Q, const float* __restrict__ BPP)
{
    const uint32_t sbase = smem_u32(sm);
    #pragma unroll 5
    for (int i = tid; i < 1280; i += NTH) {
        const int tensor = i >> 8;
        const int rem    = i & 255;
        const int b      = rem >> 6;
        const int r2     = rem & 63;
        const int k      = k0 + (r2 >> 2);
        const int d4     = r2 & 3;

        const float* gp = (tensor == 0) ? E : (tensor == 1) ? TQ
                        : (tensor == 2) ? TPP : (tensor == 3) ? R : Q;
        const int t = (tensor < 3) ? min(lo + 1 + k, RT - 1) : (lo + k);

        const size_t goff = ((size_t)(bg * NBL + b) * RT + t) * RD + d4 * 4;
        const uint32_t soff = sbase
            + (uint32_t)(tensor * TS + b * BSTR + k * RD + d4 * 4) * 4u;
        cp16(soff, gp + goff);
    }
    {
        const int b = tid >> 4;
        const int k = k0 + (tid & 15);
        const int t = min(lo + 1 + k, RT - 1);
        cp4(sbase + (uint32_t)(BPOFF + b * BPSTR + k) * 4u,
            BPP + (size_t)(bg * NBL + b) * RT + t);
    }
    cp_commit();
}

__global__ void __launch_bounds__(NTH)
retrace_fused(const float* __restrict__ Q,
              const float* __restrict__ E,
              const float* __restrict__ TQ,
              const float* __restrict__ TPP,
              const float* __restrict__ R,
              const float* __restrict__ BPP,
              float* __restrict__ out)
{
    extern __shared__ float sm[];
    __shared__ float red[2];
    __shared__ int   last_bg, last_all;

    const int tid = threadIdx.x;
    const int s   = blockIdx.x & (SEG - 1);
    const int bg  = blockIdx.x >> 4;           // 0..511

    const int lo    = s * SEGLEN;
    const int steps = min(SEGLEN, NJ - lo);    // 32, or 31 for seg 15

    copy_half(sm, tid, bg, lo, 16, E, TQ, TPP, R, Q, BPP);
    copy_half(sm, tid, bg, lo, 0,  E, TQ, TPP, R, Q, BPP);

    const int b_l = tid >> 4;
    const int d   = tid & 15;
    const int rb  = b_l * BSTR + d;
    const int bpb = BPOFF + b_l * BPSTR;

    float q0 = 0.f, P = 1.f, al = 0.f, be = 0.f, de = 0.f;

    cp_wait<1>();
    __syncthreads();

    #pragma unroll 4
    for (int k = steps - 1; k >= 16; --k) {
        const int ro = rb + k * RD;
        const float e   = sm[ro];
        const float tq  = sm[TS + ro];
        const float tpp = sm[2 * TS + ro];
        const float r   = sm[3 * TS + ro];
        const float qv  = sm[4 * TS + ro];
        const float bp  = sm[bpb + k];

        const float c = __expf(fminf(tpp - bp, 0.f));
        const float m = GAMMA * c;
        const float a = fmaf(GAMMA, fmaf(-c, tq, e), r);
        q0 = fmaf(m, q0, a);  P *= m;
        const float u = qv - q0;
        al = fmaf(u, u, al);  be = fmaf(u, P, be);  de = fmaf(P, P, de);
    }

    cp_wait<0>();
    __syncthreads();

    #pragma unroll 4
    for (int k = 15; k >= 0; --k) {
        const int ro = rb + k * RD;
        const float e   = sm[ro];
        const float tq  = sm[TS + ro];
        const float tpp = sm[2 * TS + ro];
        const float r   = sm[3 * TS + ro];
        const float qv  = sm[4 * TS + ro];
        const float bp  = sm[bpb + k];

        const float c = __expf(fminf(tpp - bp, 0.f));
        const float m = GAMMA * c;
        const float a = fmaf(GAMMA, fmaf(-c, tq, e), r);
        q0 = fmaf(m, q0, a);  P *= m;
        const float u = qv - q0;
        al = fmaf(u, u, al);  be = fmaf(u, P, be);  de = fmaf(P, P, de);
    }

    const int chain = (bg * NBL + b_l) * RD + d;   // = bg*64 + tid
    const size_t ridx = (size_t)s * BD + chain;
    g4 [ridx] = make_float4(q0, P, be, de);
    gal[ridx] = al;

    // ---- last-block-per-bg compose -------------------------------------
    __threadfence();
    if (tid == 0) {
        const unsigned int old = atomicAdd(&g_cnt_bg[bg], 1u);
        last_bg = (old == SEG - 1);
    }
    __syncthreads();
    if (!last_bg) return;
    if (tid == 0) g_cnt_bg[bg] = 0;    // reset for next graph replay

    {
        const int ch = bg * NTH + tid;         // this thread's chain
        const int b  = ch >> 4;
        const int dd = ch & 15;
        float carry = TQ[((size_t)b * RT + (RT - 1)) * RD + dd];
        float sum = 0.0f;

        #pragma unroll
        for (int s2 = SEG - 1; s2 >= 0; --s2) {
            const size_t idx = (size_t)s2 * BD + ch;
            const float4 v = g4[idx];          // A, M, be, de (L2-hot)
            const float  a2 = gal[idx];
            sum += fmaf(carry, fmaf(v.w, carry, -2.0f * v.z), a2);
            carry = fmaf(v.y, carry, v.x);
        }

        #pragma unroll
        for (int o = 16; o > 0; o >>= 1)
            sum += __shfl_down_sync(0xffffffffu, sum, o);

        const int lane = tid & 31;
        const int w    = tid >> 5;
        if (lane == 0) red[w] = sum;
        __syncthreads();

        if (tid == 0) {
            g_part[bg] = red[0] + red[1];
            __threadfence();
            const unsigned int old = atomicAdd(&g_cnt_all, 1u);
            last_all = (old == NBG - 1);
        }
        __syncthreads();
        if (!last_all) return;
        if (tid == 0) g_cnt_all = 0;   // reset for next graph replay
    }

    // ---- final reduce of 512 partials (one block, 64 threads) ----------
    {
        float t = 0.0f;
        #pragma unroll
        for (int i = tid; i < NBG; i += NTH) t += g_part[i];

        #pragma unroll
        for (int o = 16; o > 0; o >>= 1)
            t += __shfl_down_sync(0xffffffffu, t, o);

        const int lane = tid & 31;
        const int w    = tid >> 5;
        if (lane == 0) red[w] = t;
        __syncthreads();

        if (tid == 0) {
            const float invN = 1.0f / ((float)RB * (float)NJ * (float)RD);
            out[0] = (red[0] + red[1]) * invN;
        }
    }
}

extern "C" void kernel_launch(void* const* d_in, const int* in_sizes, int n_in,
                              void* d_out, int out_size)
{
    const float* Q   = (const float*)d_in[0];
    const float* E   = (const float*)d_in[1];
    const float* TQ  = (const float*)d_in[2];
    const float* R   = (const float*)d_in[3];
    const float* TPP = (const float*)d_in[4];
    const float* BPP = (const float*)d_in[5];
    float* out = (float*)d_out;

    // 512 b-groups x 16 segments = 8192 blocks of 64 threads
    retrace_fused<<<NBG * SEG, NTH, SMEM_BYTES>>>(Q, E, TQ, TPP, R, BPP, out);
}

// round 11
// speedup vs baseline: 1.4005x; 1.4005x over previous
#include <cuda_runtime.h>
#include <cstdint>

// Retrace_9844065042706 — affine-segment scan, cp.async staging (split kernels).
// Pass1: block = 4 b x 16 d over a 32-step segment, 64 threads, 42.8KB smem
// -> 5 resident blocks/SM. Copy indexing strength-reduced: per-thread chunk
// coordinates are constants (b=j, k=k0+(tid>>2), d4=tid&3), so the stage is
// 20 unrolled cp16's with precomputed addresses.
// Pass2 (R9): 4 lanes/chain serial-compose 4 segments each + width-4 shuffle tree.

#define RB 2048
#define RT 512
#define RD 16
#define SEG 16
#define SEGLEN 32
#define NJ (RT - 1)            // 511
#define BD (RB * RD)           // 32768 chains
#define NBL 4                  // b's per block
#define NTH 64                 // threads (4 b x 16 d)

// smem (floats): 5 tensors [4][32][16] (+16 pad per b), then bp [4][33]
#define BSTR  528
#define TS    (NBL * BSTR)     // 2112
#define BPOFF (5 * TS)         // 10560
#define BPSTR 33
#define SMEM_FLOATS (BPOFF + NBL * BPSTR)   // 10692 -> 42768 B
#define SMEM_BYTES  (SMEM_FLOATS * 4)

static constexpr float GAMMA = 0.99f;

// Dense scratch, seg-major (chain-contiguous): 10 MB
__device__ float4 g4 [(size_t)SEG * BD];   // {A, M, beta, delta}
__device__ float  gal[(size_t)SEG * BD];   // alpha

__device__ __forceinline__ void cp16(uint32_t s, const void* g) {
    asm volatile("cp.async.cg.shared.global [%0], [%1], 16;" :: "r"(s), "l"(g));
}
__device__ __forceinline__ void cp4(uint32_t s, const void* g) {
    asm volatile("cp.async.ca.shared.global [%0], [%1], 4;" :: "r"(s), "l"(g));
}
__device__ __forceinline__ void cp_commit() { asm volatile("cp.async.commit_group;"); }
template <int N>
__device__ __forceinline__ void cp_wait() {
    asm volatile("cp.async.wait_group %0;" :: "n"(N));
}
__device__ __forceinline__ uint32_t smem_u32(const void* p) {
    return (uint32_t)__cvta_generic_to_shared(p);
}

// Stage rows [k0, k0+16): thread tid owns chunk (b=j, k=k0+(tid>>2), d4=tid&3)
// for j = 0..3, per tensor. 20 cp16 + 1 cp4, addresses precomputed.
__device__ __forceinline__ void copy_half(
    float* sm, int tid, int bg, int lo, int k0,
    const float* __restrict__ E, const float* __restrict__ TQ,
    const float* __restrict__ TPP, const float* __restrict__ R,
    const float* __restrict__ Q, const float* __restrict__ BPP)
{
    const uint32_t sbase = smem_u32(sm);
    const int krow = tid >> 2;            // 0..15
    const int d4f  = (tid & 3) * 4;       // float offset within row
    const int k    = k0 + krow;
    const int t1   = min(lo + 1 + k, RT - 1);   // rows for E, TQ, TPP
    const int t0   = lo + k;                    // rows for R, Q
    const uint32_t so = sbase + (uint32_t)(k * RD + d4f) * 4u;
    const size_t gb = (size_t)(bg * NBL) * RT * RD + d4f;

#define CP_T(tn, gp, t)                                                        \
    {                                                                          \
        const float* g = (gp) + gb + (size_t)(t) * RD;                         \
        cp16(so + (uint32_t)((tn) * TS + 0 * BSTR) * 4u, g + 0 * RT * RD);     \
        cp16(so + (uint32_t)((tn) * TS + 1 * BSTR) * 4u, g + 1 * RT * RD);     \
        cp16(so + (uint32_t)((tn) * TS + 2 * BSTR) * 4u, g + 2 * RT * RD);     \
        cp16(so + (uint32_t)((tn) * TS + 3 * BSTR) * 4u, g + 3 * RT * RD);     \
    }
    CP_T(0, E,   t1)
    CP_T(1, TQ,  t1)
    CP_T(2, TPP, t1)
    CP_T(3, R,   t0)
    CP_T(4, Q,   t0)
#undef CP_T

    // bp: 64 entries, one per thread
    {
        const int b  = tid >> 4;
        const int kk = k0 + (tid & 15);
        const int tb = min(lo + 1 + kk, RT - 1);
        cp4(sbase + (uint32_t)(BPOFF + b * BPSTR + kk) * 4u,
            BPP + (size_t)(bg * NBL + b) * RT + tb);
    }
    cp_commit();
}

__global__ void __launch_bounds__(NTH)
retrace_pass1(const float* __restrict__ Q,
              const float* __restrict__ E,
              const float* __restrict__ TQ,
              const float* __restrict__ TPP,
              const float* __restrict__ R,
              const float* __restrict__ BPP,
              float* __restrict__ out)
{
    extern __shared__ float sm[];
    const int tid = threadIdx.x;
    const int s   = blockIdx.x & (SEG - 1);
    const int bg  = blockIdx.x >> 4;           // 0..511

    if (blockIdx.x == 0 && tid == 0) out[0] = 0.0f;

    const int lo    = s * SEGLEN;
    const int steps = min(SEGLEN, NJ - lo);    // 32, or 31 for seg 15

    copy_half(sm, tid, bg, lo, 16, E, TQ, TPP, R, Q, BPP);
    copy_half(sm, tid, bg, lo, 0,  E, TQ, TPP, R, Q, BPP);

    const int b_l = tid >> 4;
    const int d   = tid & 15;
    const int rb  = b_l * BSTR + d;
    const int bpb = BPOFF + b_l * BPSTR;

    float q0 = 0.f, P = 1.f, al = 0.f, be = 0.f, de = 0.f;

    cp_wait<1>();
    __syncthreads();

    #pragma unroll 4
    for (int k = steps - 1; k >= 16; --k) {
        const int ro = rb + k * RD;
        const float e   = sm[ro];
        const float tq  = sm[TS + ro];
        const float tpp = sm[2 * TS + ro];
        const float r   = sm[3 * TS + ro];
        const float qv  = sm[4 * TS + ro];
        const float bp  = sm[bpb + k];

        const float c = __expf(fminf(tpp - bp, 0.f));
        const float m = GAMMA * c;
        const float a = fmaf(GAMMA, fmaf(-c, tq, e), r);
        q0 = fmaf(m, q0, a);  P *= m;
        const float u = qv - q0;
        al = fmaf(u, u, al);  be = fmaf(u, P, be);  de = fmaf(P, P, de);
    }

    cp_wait<0>();
    __syncthreads();

    #pragma unroll 4
    for (int k = 15; k >= 0; --k) {
        const int ro = rb + k * RD;
        const float e   = sm[ro];
        const float tq  = sm[TS + ro];
        const float tpp = sm[2 * TS + ro];
        const float r   = sm[3 * TS + ro];
        const float qv  = sm[4 * TS + ro];
        const float bp  = sm[bpb + k];

        const float c = __expf(fminf(tpp - bp, 0.f));
        const float m = GAMMA * c;
        const float a = fmaf(GAMMA, fmaf(-c, tq, e), r);
        q0 = fmaf(m, q0, a);  P *= m;
        const float u = qv - q0;
        al = fmaf(u, u, al);  be = fmaf(u, P, be);  de = fmaf(P, P, de);
    }

    const int chain = (bg * NBL + b_l) * RD + d;
    const size_t idx = (size_t)s * BD + chain;
    g4 [idx] = make_float4(q0, P, be, de);
    gal[idx] = al;
}

// ---------------------------------------------------------------------------
// Pass 2: 4 lanes per chain (sub handles segs [4sub, 4sub+4)); serial fold
// then 2-step width-4 shuffle tree. Compose (X lower-s, Y higher-s):
//   al'' = alY + alX - 2 beX AY + deX AY^2
//   be'' = beY + (beX - deX AY) MY
//   de'' = deY + deX MY^2
//   A''  = AX + MX AY ;  M'' = MX MY
// ---------------------------------------------------------------------------
__global__ void __launch_bounds__(128)
retrace_pass2(const float* __restrict__ TQ, float* __restrict__ out)
{
    const int gid   = blockIdx.x * blockDim.x + threadIdx.x;  // 0..4*BD-1
    const int chain = gid >> 2;
    const int sub   = gid & 3;

    const int shi = sub * 4 + 3;
    size_t idx = (size_t)shi * BD + chain;
    float4 v = g4[idx];
    float A = v.x, M = v.y, be = v.z, de = v.w;
    float al = gal[idx];

    #pragma unroll
    for (int i = 2; i >= 0; --i) {
        idx = (size_t)(sub * 4 + i) * BD + chain;
        const float4 x = g4[idx];
        const float alx = gal[idx];

        const float nal = al + alx - 2.0f * x.z * A + x.w * A * A;
        const float nbe = be + (x.z - x.w * A) * M;
        const float nde = de + x.w * M * M;
        const float nA  = fmaf(x.y, A, x.x);
        const float nM  = x.y * M;
        al = nal; be = nbe; de = nde; A = nA; M = nM;
    }

    #pragma unroll
    for (int k = 1; k < 4; k <<= 1) {
        const float oA  = __shfl_down_sync(0xffffffffu, A,  k, 4);
        const float oM  = __shfl_down_sync(0xffffffffu, M,  k, 4);
        const float oal = __shfl_down_sync(0xffffffffu, al, k, 4);
        const float obe = __shfl_down_sync(0xffffffffu, be, k, 4);
        const float ode = __shfl_down_sync(0xffffffffu, de, k, 4);

        const float nal = oal + al - 2.0f * be * oA + de * oA * oA;
        const float nbe = obe + (be - de * oA) * oM;
        const float nde = ode + de * oM * oM;
        const float nA  = fmaf(M, oA, A);
        const float nM  = M * oM;
        al = nal; be = nbe; de = nde; A = nA; M = nM;
    }

    float sum = 0.0f;
    if (sub == 0) {
        const int b = chain >> 4;
        const int d = chain & 15;
        const float carry = TQ[((size_t)b * RT + (RT - 1)) * RD + d];
        sum = fmaf(carry, fmaf(de, carry, -2.0f * be), al);
    }

    #pragma unroll
    for (int o = 16; o > 0; o >>= 1)
        sum += __shfl_down_sync(0xffffffffu, sum, o);

    __shared__ float ws[4];
    const int lane = threadIdx.x & 31;
    const int w    = threadIdx.x >> 5;
    if (lane == 0) ws[w] = sum;
    __syncthreads();

    if (w == 0) {
        float x = (lane < 4) ? ws[lane] : 0.0f;
        #pragma unroll
        for (int o = 2; o > 0; o >>= 1)
            x += __shfl_down_sync(0xffffffffu, x, o);
        if (lane == 0) {
            const float invN = 1.0f / ((float)RB * (float)NJ * (float)RD);
            atomicAdd(out, x * invN);
        }
    }
}

extern "C" void kernel_launch(void* const* d_in, const int* in_sizes, int n_in,
                              void* d_out, int out_size)
{
    const float* Q   = (const float*)d_in[0];
    const float* E   = (const float*)d_in[1];
    const float* TQ  = (const float*)d_in[2];
    const float* R   = (const float*)d_in[3];
    const float* TPP = (const float*)d_in[4];
    const float* BPP = (const float*)d_in[5];
    float* out = (float*)d_out;

    // Pass 1: 512 b-groups x 16 segments = 8192 blocks of 64 threads
    retrace_pass1<<<(RB / NBL) * SEG, NTH, SMEM_BYTES>>>(Q, E, TQ, TPP, R, BPP, out);

    // Pass 2: 4 lanes per chain = 131072 threads
    retrace_pass2<<<(BD * 4) / 128, 128>>>(TQ, out);
}